// round 6
// baseline (speedup 1.0000x reference)
#include <cuda_runtime.h>
#include <math.h>

#define G3 32768
#define NVIEW 8

__device__ __forceinline__ float elu_f(float x)  { return x > 0.f ? x : (__expf(x) - 1.f); }
__device__ __forceinline__ float sigm_f(float x) { return 1.f / (1.f + __expf(-x)); }

__global__ __launch_bounds__(128, 3)
void ibr_agg_tpv2_kernel(
    const float* __restrict__ features,   // (B,N,32,G3)
    const float* __restrict__ mask,       // (B,N,1,G3)
    const float* __restrict__ depth,      // (B,N,1,G3)
    const float* __restrict__ vdir,       // (B,N,3,G3)
    const float* __restrict__ g_rw1, const float* __restrict__ g_rb1,   // (16,4),(16)
    const float* __restrict__ g_rw2, const float* __restrict__ g_rb2,   // (32,16),(32)
    const float* __restrict__ g_bw1, const float* __restrict__ g_bb1,   // (64,96),(64)
    const float* __restrict__ g_bw2, const float* __restrict__ g_bb2,   // (32,64),(32)
    const float* __restrict__ g_vw1, const float* __restrict__ g_vb1,   // (32,32),(32)
    const float* __restrict__ g_vw2, const float* __restrict__ g_vb2,   // (33,32),(33)
    const float* __restrict__ g_v2w1, const float* __restrict__ g_v2b1, // (32,32),(32)
    const float* __restrict__ g_v2w2, const float* __restrict__ g_v2b2, // (1,32),(1)
    const float* __restrict__ g_sw,  const float* __restrict__ g_sb,    // (32,65),(32)
    float* __restrict__ out)              // (B,32,G3)
{
    // Weights row-major (out, in): in-dim contiguous -> uniform-broadcast LDS.128.
    __shared__ __align__(16) float s_rw1[16 * 4];
    __shared__ __align__(16) float s_rb1[16];
    __shared__ __align__(16) float s_rw2[32 * 16];
    __shared__ __align__(16) float s_rb2[32];
    __shared__ __align__(16) float s_bw1f[64 * 32];   // base_w1 cols 64..95 (feat part)
    __shared__ __align__(16) float s_bw2[32 * 64];
    __shared__ __align__(16) float s_bb2[32];
    __shared__ __align__(16) float s_vw1[32 * 32];
    __shared__ __align__(16) float s_vb1[32];
    __shared__ __align__(16) float s_vw2[33 * 32];
    __shared__ __align__(16) float s_vb2[36];
    __shared__ __align__(16) float s_v2w1[32 * 32];
    __shared__ __align__(16) float s_v2b1[32];
    __shared__ __align__(16) float s_v2w2[32];
    __shared__ __align__(16) float s_sw[32 * 68];     // stat_w rows padded 65->68
    __shared__ __align__(16) float s_sb[32];

    const int tid = threadIdx.x;

    for (int i = tid; i < 16 * 4;  i += 128) s_rw1[i] = g_rw1[i];
    if (tid < 16) s_rb1[tid] = g_rb1[tid];
    for (int i = tid; i < 32 * 16; i += 128) s_rw2[i] = g_rw2[i];
    if (tid < 32) s_rb2[tid] = g_rb2[tid];
    for (int i = tid; i < 64 * 32; i += 128) { int o = i >> 5, c = i & 31; s_bw1f[i] = g_bw1[o * 96 + 64 + c]; }
    for (int i = tid; i < 32 * 64; i += 128) s_bw2[i] = g_bw2[i];
    if (tid < 32) s_bb2[tid] = g_bb2[tid];
    for (int i = tid; i < 32 * 32; i += 128) s_vw1[i] = g_vw1[i];
    if (tid < 32) s_vb1[tid] = g_vb1[tid];
    for (int i = tid; i < 33 * 32; i += 128) s_vw2[i] = g_vw2[i];
    if (tid < 33) s_vb2[tid] = g_vb2[tid];
    for (int i = tid; i < 32 * 32; i += 128) s_v2w1[i] = g_v2w1[i];
    if (tid < 32) s_v2b1[tid] = g_v2b1[tid];
    if (tid < 32) s_v2w2[tid] = g_v2w2[tid];
    for (int i = tid; i < 32 * 65; i += 128) { int o = i / 65, c = i % 65; s_sw[o * 68 + c] = g_sw[i]; }
    if (tid < 32) s_sb[tid] = g_sb[tid];
    __syncthreads();

    const float EPS  = 1e-8f;
    const float v2b2 = __ldg(g_v2b2);

    const int gv = blockIdx.x * 128 + tid;   // [0, 65536): (b, voxel)
    const int b  = gv >> 15;
    const int v  = gv & (G3 - 1);

    // ---- mask sum ----
    float msum = 0.f;
    #pragma unroll
    for (int n = 0; n < NVIEW; ++n) msum += __ldg(&mask[(b * NVIEW + n) * G3 + v]);
    const float minv = 1.f / (msum + EPS);
    const float ws   = msum * minv;

    // ================= phase 1: Sum(w f), Sum(w f^2) over views =================
    float A1[32], A2[32];
    #pragma unroll
    for (int c = 0; c < 32; ++c) { A1[c] = 0.f; A2[c] = 0.f; }

    #pragma unroll 1
    for (int n = 0; n < NVIEW; ++n) {
        const int bn = b * NVIEW + n;
        const float i0 = __ldg(&vdir[(bn * 3 + 0) * G3 + v]);
        const float i1 = __ldg(&vdir[(bn * 3 + 1) * G3 + v]);
        const float i2 = __ldg(&vdir[(bn * 3 + 2) * G3 + v]);
        const float i3 = __ldg(&depth[bn * G3 + v]);
        const float wn = __ldg(&mask[bn * G3 + v]) * minv;

        float h16[16];
        #pragma unroll
        for (int o = 0; o < 16; ++o) {
            const float4 w = *reinterpret_cast<const float4*>(&s_rw1[o * 4]);
            h16[o] = elu_f(s_rb1[o] + w.x * i0 + w.y * i1 + w.z * i2 + w.w * i3);
        }

        const float* fbase = &features[(bn * 32) * G3 + v];
        #pragma unroll
        for (int c = 0; c < 32; ++c) {
            float acc = s_rb2[c];
            #pragma unroll
            for (int o = 0; o < 16; o += 4) {
                const float4 w = *reinterpret_cast<const float4*>(&s_rw2[c * 16 + o]);
                acc += w.x * h16[o] + w.y * h16[o + 1] + w.z * h16[o + 2] + w.w * h16[o + 3];
            }
            const float f = __ldg(&fbase[c * G3]) + elu_f(acc);
            A1[c] += wn * f;
            A2[c] += wn * f * f;
        }
    }

    // mean / var  (var = Sum w f^2 - mean^2 (2 - ws))
    #pragma unroll
    for (int c = 0; c < 32; ++c) {
        const float mc = A1[c];
        A2[c] = A2[c] - mc * mc * (2.f - ws);   // A1 = mean, A2 = var
    }

    // ---- hbase[o] = bb1[o] + bw1[o,0:32].mean + bw1[o,32:64].var ----
    float hbase[64];    // local (L1-resident), read 64x per view in phase 2
    #pragma unroll 1
    for (int o = 0; o < 64; ++o) {
        float acc = __ldg(&g_bb1[o]);
        const float4* wr = reinterpret_cast<const float4*>(&g_bw1[o * 96]);
        #pragma unroll
        for (int c = 0; c < 32; c += 4) {
            const float4 wm = __ldg(&wr[c / 4]);
            const float4 wv = __ldg(&wr[8 + c / 4]);
            acc += wm.x * A1[c] + wm.y * A1[c + 1] + wm.z * A1[c + 2] + wm.w * A1[c + 3];
            acc += wv.x * A2[c] + wv.y * A2[c + 1] + wv.z * A2[c + 2] + wv.w * A2[c + 3];
        }
        hbase[o] = acc;
    }

    // ================= phase 2: per-view MLPs; S, U=Sum(vis2 x), V=Sum(vis2 x^2) =================
    float U[32], Vv[32];
    float S = 0.f;
    #pragma unroll
    for (int c = 0; c < 32; ++c) { U[c] = 0.f; Vv[c] = 0.f; }

    #pragma unroll 1
    for (int n = 0; n < NVIEW; ++n) {
        const int bn = b * NVIEW + n;
        const float mval = __ldg(&mask[bn * G3 + v]);
        const float wn   = mval * minv;

        // --- recompute rde + f (cheaper than caching 1KB/thread in local) ---
        const float i0 = __ldg(&vdir[(bn * 3 + 0) * G3 + v]);
        const float i1 = __ldg(&vdir[(bn * 3 + 1) * G3 + v]);
        const float i2 = __ldg(&vdir[(bn * 3 + 2) * G3 + v]);
        const float i3 = __ldg(&depth[bn * G3 + v]);

        float h16[16];
        #pragma unroll
        for (int o = 0; o < 16; ++o) {
            const float4 w = *reinterpret_cast<const float4*>(&s_rw1[o * 4]);
            h16[o] = elu_f(s_rb1[o] + w.x * i0 + w.y * i1 + w.z * i2 + w.w * i3);
        }

        float f[32];   // f -> t -> t2 (reused)
        const float* fbase = &features[(bn * 32) * G3 + v];
        #pragma unroll
        for (int c = 0; c < 32; ++c) {
            float acc = s_rb2[c];
            #pragma unroll
            for (int o = 0; o < 16; o += 4) {
                const float4 w = *reinterpret_cast<const float4*>(&s_rw2[c * 16 + o]);
                acc += w.x * h16[o] + w.y * h16[o + 1] + w.z * h16[o + 2] + w.w * h16[o + 3];
            }
            f[c] = __ldg(&fbase[c * G3]) + elu_f(acc);
        }

        // --- base: h = elu(hbase + bw1f.f) (64) ; xx = elu(bb2 + bw2.h) (32), 8-chunked ---
        float xx[32];
        #pragma unroll
        for (int j = 0; j < 32; ++j) xx[j] = s_bb2[j];

        #pragma unroll 1
        for (int oc = 0; oc < 8; ++oc) {
            const int o8 = oc * 8;
            float h[8];
            #pragma unroll
            for (int k = 0; k < 8; ++k) {
                float acc = hbase[o8 + k];
                const float* wr = &s_bw1f[(o8 + k) * 32];
                #pragma unroll
                for (int c = 0; c < 32; c += 4) {
                    const float4 w = *reinterpret_cast<const float4*>(&wr[c]);
                    acc += w.x * f[c] + w.y * f[c + 1] + w.z * f[c + 2] + w.w * f[c + 3];
                }
                h[k] = elu_f(acc);
            }
            #pragma unroll
            for (int j = 0; j < 32; ++j) {
                const float* wr = &s_bw2[j * 64 + o8];
                const float4 wa = *reinterpret_cast<const float4*>(&wr[0]);
                const float4 wb = *reinterpret_cast<const float4*>(&wr[4]);
                xx[j] += wa.x * h[0] + wa.y * h[1] + wa.z * h[2] + wa.w * h[3]
                       + wb.x * h[4] + wb.y * h[5] + wb.z * h[6] + wb.w * h[7];
            }
        }
        #pragma unroll
        for (int j = 0; j < 32; ++j) xx[j] = elu_f(xx[j]);

        // --- vis: t = xx*w ; hv = elu(vw1.t) full ; xx += elu(vb2 + vw2.hv) ; va ---
        #pragma unroll
        for (int c = 0; c < 32; ++c) f[c] = xx[c] * wn;     // t

        float hv[32];
        #pragma unroll
        for (int o = 0; o < 32; ++o) {
            float acc = s_vb1[o];
            const float* wr = &s_vw1[o * 32];
            #pragma unroll
            for (int c = 0; c < 32; c += 4) {
                const float4 w = *reinterpret_cast<const float4*>(&wr[c]);
                acc += w.x * f[c] + w.y * f[c + 1] + w.z * f[c + 2] + w.w * f[c + 3];
            }
            hv[o] = elu_f(acc);
        }

        #pragma unroll
        for (int j = 0; j < 32; ++j) {
            float acc = s_vb2[j];
            const float* wr = &s_vw2[j * 32];
            #pragma unroll
            for (int c = 0; c < 32; c += 4) {
                const float4 w = *reinterpret_cast<const float4*>(&wr[c]);
                acc += w.x * hv[c] + w.y * hv[c + 1] + w.z * hv[c + 2] + w.w * hv[c + 3];
            }
            xx[j] += elu_f(acc);                             // x = x + x_res
        }
        float va = s_vb2[32];
        {
            const float* wr = &s_vw2[32 * 32];
            #pragma unroll
            for (int c = 0; c < 32; c += 4) {
                const float4 w = *reinterpret_cast<const float4*>(&wr[c]);
                va += w.x * hv[c] + w.y * hv[c + 1] + w.z * hv[c + 2] + w.w * hv[c + 3];
            }
        }
        const float vis = sigm_f(elu_f(va)) * mval;

        // --- vis2: t2 = xx*vis ; s2 = v2b2 + v2w2.elu(v2w1.t2) ---
        #pragma unroll
        for (int c = 0; c < 32; ++c) f[c] = xx[c] * vis;     // t2

        float s2 = v2b2;
        #pragma unroll 1
        for (int o = 0; o < 32; ++o) {
            float acc = s_v2b1[o];
            const float* wr = &s_v2w1[o * 32];
            #pragma unroll
            for (int c = 0; c < 32; c += 4) {
                const float4 w = *reinterpret_cast<const float4*>(&wr[c]);
                acc += w.x * f[c] + w.y * f[c + 1] + w.z * f[c + 2] + w.w * f[c + 3];
            }
            s2 += s_v2w2[o] * elu_f(acc);
        }
        const float vis2 = sigm_f(s2) * mval;

        S += vis2;
        #pragma unroll
        for (int c = 0; c < 32; ++c) {
            U[c]  += vis2 * xx[c];
            Vv[c] += vis2 * xx[c] * xx[c];
        }
    }

    // ================= second mean/var + stat head =================
    const float Sinv  = 1.f / (S + EPS);
    const float w2s   = S * Sinv;
    const float wmean = w2s * 0.125f;

    #pragma unroll
    for (int c = 0; c < 32; ++c) {
        const float m2 = U[c] * Sinv;
        U[c]  = m2;                                   // mean2
        Vv[c] = Vv[c] * Sinv - m2 * m2 * (2.f - w2s); // var2
    }

    #pragma unroll 1
    for (int o = 0; o < 32; ++o) {
        float acc = s_sb[o];
        const float* wr = &s_sw[o * 68];
        #pragma unroll
        for (int c = 0; c < 32; c += 4) {
            const float4 wm = *reinterpret_cast<const float4*>(&wr[c]);
            const float4 wv = *reinterpret_cast<const float4*>(&wr[32 + c]);
            acc += wm.x * U[c]  + wm.y * U[c + 1]  + wm.z * U[c + 2]  + wm.w * U[c + 3];
            acc += wv.x * Vv[c] + wv.y * Vv[c + 1] + wv.z * Vv[c + 2] + wv.w * Vv[c + 3];
        }
        acc += wr[64] * wmean;
        out[(b * 32 + o) * G3 + v] = elu_f(acc);
    }
}

extern "C" void kernel_launch(void* const* d_in, const int* in_sizes, int n_in,
                              void* d_out, int out_size) {
    (void)in_sizes; (void)n_in; (void)out_size;
    const float* features = (const float*)d_in[0];
    const float* mask     = (const float*)d_in[1];
    const float* depth    = (const float*)d_in[2];
    const float* vdir     = (const float*)d_in[3];
    const float* rde_w1   = (const float*)d_in[4];
    const float* rde_b1   = (const float*)d_in[5];
    const float* rde_w2   = (const float*)d_in[6];
    const float* rde_b2   = (const float*)d_in[7];
    const float* base_w1  = (const float*)d_in[8];
    const float* base_b1  = (const float*)d_in[9];
    const float* base_w2  = (const float*)d_in[10];
    const float* base_b2  = (const float*)d_in[11];
    const float* vis_w1   = (const float*)d_in[12];
    const float* vis_b1   = (const float*)d_in[13];
    const float* vis_w2   = (const float*)d_in[14];
    const float* vis_b2   = (const float*)d_in[15];
    const float* vis2_w1  = (const float*)d_in[16];
    const float* vis2_b1  = (const float*)d_in[17];
    const float* vis2_w2  = (const float*)d_in[18];
    const float* vis2_b2  = (const float*)d_in[19];
    const float* stat_w   = (const float*)d_in[20];
    const float* stat_b   = (const float*)d_in[21];
    float* out = (float*)d_out;

    ibr_agg_tpv2_kernel<<<512, 128>>>(
        features, mask, depth, vdir,
        rde_w1, rde_b1, rde_w2, rde_b2,
        base_w1, base_b1, base_w2, base_b2,
        vis_w1, vis_b1, vis_w2, vis_b2,
        vis2_w1, vis2_b1, vis2_w2, vis2_b2,
        stat_w, stat_b, out);
}

// round 7
// speedup vs baseline: 1.0583x; 1.0583x over previous
#include <cuda_runtime.h>
#include <math.h>

#define G3 32768
#define NVIEW 8
#define FULL 0xFFFFFFFFu

__device__ __forceinline__ float elu_f(float x)  { return x > 0.f ? x : (__expf(x) - 1.f); }
__device__ __forceinline__ float sigm_f(float x) { return 1.f / (1.f + __expf(-x)); }

template<int N>
__device__ __forceinline__ float sdot(const float* __restrict__ wr, const float* __restrict__ x) {
    float acc = 0.f;
    #pragma unroll
    for (int c = 0; c < N; c += 4) {
        const float4 w = *reinterpret_cast<const float4*>(wr + c);
        acc += w.x * x[c] + w.y * x[c + 1] + w.z * x[c + 2] + w.w * x[c + 3];
    }
    return acc;
}

__global__ __launch_bounds__(128, 3)
void ibr_agg_pair_kernel(
    const float* __restrict__ features,   // (B,N,32,G3)
    const float* __restrict__ mask,       // (B,N,1,G3)
    const float* __restrict__ depth,      // (B,N,1,G3)
    const float* __restrict__ vdir,       // (B,N,3,G3)
    const float* __restrict__ g_rw1, const float* __restrict__ g_rb1,   // (16,4),(16)
    const float* __restrict__ g_rw2, const float* __restrict__ g_rb2,   // (32,16),(32)
    const float* __restrict__ g_bw1, const float* __restrict__ g_bb1,   // (64,96),(64)
    const float* __restrict__ g_bw2, const float* __restrict__ g_bb2,   // (32,64),(32)
    const float* __restrict__ g_vw1, const float* __restrict__ g_vb1,   // (32,32),(32)
    const float* __restrict__ g_vw2, const float* __restrict__ g_vb2,   // (33,32),(33)
    const float* __restrict__ g_v2w1, const float* __restrict__ g_v2b1, // (32,32),(32)
    const float* __restrict__ g_v2w2, const float* __restrict__ g_v2b2, // (1,32),(1)
    const float* __restrict__ g_sw,  const float* __restrict__ g_sb,    // (32,65),(32)
    float* __restrict__ out)              // (B,32,G3)
{
    __shared__ __align__(16) float s_rw1[16 * 4];
    __shared__ __align__(16) float s_rb1[16];
    __shared__ __align__(16) float s_rw2[32 * 16];
    __shared__ __align__(16) float s_rb2[32];
    __shared__ __align__(16) float s_bw1f[64 * 32];   // base_w1 cols 64..95 (feat part)
    __shared__ __align__(16) float s_bw2[32 * 64];
    __shared__ __align__(16) float s_bb2[32];
    __shared__ __align__(16) float s_vw1[32 * 32];
    __shared__ __align__(16) float s_vb1[32];
    __shared__ __align__(16) float s_vw2[33 * 32];
    __shared__ __align__(16) float s_vb2[36];
    __shared__ __align__(16) float s_v2w1[32 * 32];
    __shared__ __align__(16) float s_v2b1[32];
    __shared__ __align__(16) float s_v2w2[32];
    __shared__ __align__(16) float s_sw[32 * 68];     // stat_w rows padded 65->68
    __shared__ __align__(16) float s_sb[32];

    const int tid = threadIdx.x;

    for (int i = tid; i < 16 * 4;  i += 128) s_rw1[i] = g_rw1[i];
    if (tid < 16) s_rb1[tid] = g_rb1[tid];
    for (int i = tid; i < 32 * 16; i += 128) s_rw2[i] = g_rw2[i];
    if (tid < 32) s_rb2[tid] = g_rb2[tid];
    for (int i = tid; i < 64 * 32; i += 128) { int o = i >> 5, c = i & 31; s_bw1f[i] = g_bw1[o * 96 + 64 + c]; }
    for (int i = tid; i < 32 * 64; i += 128) s_bw2[i] = g_bw2[i];
    if (tid < 32) s_bb2[tid] = g_bb2[tid];
    for (int i = tid; i < 32 * 32; i += 128) s_vw1[i] = g_vw1[i];
    if (tid < 32) s_vb1[tid] = g_vb1[tid];
    for (int i = tid; i < 33 * 32; i += 128) s_vw2[i] = g_vw2[i];
    if (tid < 33) s_vb2[tid] = g_vb2[tid];
    for (int i = tid; i < 32 * 32; i += 128) s_v2w1[i] = g_v2w1[i];
    if (tid < 32) s_v2b1[tid] = g_v2b1[tid];
    if (tid < 32) s_v2w2[tid] = g_v2w2[tid];
    for (int i = tid; i < 32 * 65; i += 128) { int o = i / 65, c = i % 65; s_sw[o * 68 + c] = g_sw[i]; }
    if (tid < 32) s_sb[tid] = g_sb[tid];
    __syncthreads();

    const float EPS  = 1e-8f;
    const float v2b2 = __ldg(g_v2b2);

    // Two threads per voxel: lane pairs (l, l^1). h = which 16-channel half I own.
    const int gt = blockIdx.x * 128 + tid;   // [0, 131072)
    const int gv = gt >> 1;                  // voxel site [0, 65536)
    const int h  = gt & 1;
    const int b  = gv >> 15;
    const int v  = gv & (G3 - 1);
    const int hc16 = h * 16;                 // my channel base
    const int oc16 = 16 - hc16;              // partner channel base (for outputs of 32)
    const int hc32 = h * 32;
    const int oc32 = 32 - hc32;
    const int hc8  = h * 8;

    // ---- mask sum (both threads of a pair compute identically) ----
    float msum = 0.f;
    #pragma unroll
    for (int n = 0; n < NVIEW; ++n) msum += __ldg(&mask[(b * NVIEW + n) * G3 + v]);
    const float minv = 1.f / (msum + EPS);
    const float ws   = msum * minv;

    // ================= phase 1: A1=Sum(w f), A2=Sum(w f^2) over own 16 channels ===========
    float A1[16], A2[16];
    #pragma unroll
    for (int c = 0; c < 16; ++c) { A1[c] = 0.f; A2[c] = 0.f; }

    #pragma unroll 1
    for (int n = 0; n < NVIEW; ++n) {
        const int bn = b * NVIEW + n;
        const float i0 = __ldg(&vdir[(bn * 3 + 0) * G3 + v]);
        const float i1 = __ldg(&vdir[(bn * 3 + 1) * G3 + v]);
        const float i2 = __ldg(&vdir[(bn * 3 + 2) * G3 + v]);
        const float i3 = __ldg(&depth[bn * G3 + v]);
        const float wn = __ldg(&mask[bn * G3 + v]) * minv;

        // rde1: I own 8 of the 16 hidden units
        float h16o[8];
        #pragma unroll
        for (int j = 0; j < 8; ++j) {
            const int o = hc8 + j;
            const float4 w = *reinterpret_cast<const float4*>(&s_rw1[o * 4]);
            h16o[j] = elu_f(s_rb1[o] + w.x * i0 + w.y * i1 + w.z * i2 + w.w * i3);
        }

        // rde2 + feats: own 16 channels, pairwise partial exchange
        const float* fbase = &features[(bn * 32 + hc16) * G3 + v];
        #pragma unroll
        for (int j = 0; j < 16; ++j) {
            const int om = hc16 + j, ot = oc16 + j;
            const float pm = sdot<8>(&s_rw2[om * 16 + hc8], h16o);
            const float pt = sdot<8>(&s_rw2[ot * 16 + hc8], h16o);
            const float f  = __ldg(&fbase[j * G3])
                           + elu_f(s_rb2[om] + pm + __shfl_xor_sync(FULL, pt, 1));
            A1[j] += wn * f;
            A2[j] += wn * f * f;
        }
    }

    // mean / var (own 16): var = A2 - mean^2 (2 - ws)
    #pragma unroll
    for (int c = 0; c < 16; ++c) {
        const float mc = A1[c];
        A2[c] = A2[c] - mc * mc * (2.f - ws);   // A1 = mean, A2 = var
    }

    // ---- hbase (my 32 of 64): bb1[o] + bw1[o,0:32].mean + bw1[o,32:64].var ----
    float hbase[32];   // local array (dynamic store loop); reads below are static-indexed
    #pragma unroll 1
    for (int j = 0; j < 32; ++j) {
        const int om = hc32 + j, ot = oc32 + j;
        float pm = 0.f, pt = 0.f;
        const float* rm = &g_bw1[om * 96];
        const float* rt = &g_bw1[ot * 96];
        #pragma unroll
        for (int c = 0; c < 16; c += 4) {
            const float4 wm1 = __ldg(reinterpret_cast<const float4*>(rm + hc16 + c));
            const float4 wm2 = __ldg(reinterpret_cast<const float4*>(rm + 32 + hc16 + c));
            const float4 wt1 = __ldg(reinterpret_cast<const float4*>(rt + hc16 + c));
            const float4 wt2 = __ldg(reinterpret_cast<const float4*>(rt + 32 + hc16 + c));
            pm += wm1.x * A1[c] + wm1.y * A1[c + 1] + wm1.z * A1[c + 2] + wm1.w * A1[c + 3];
            pm += wm2.x * A2[c] + wm2.y * A2[c + 1] + wm2.z * A2[c + 2] + wm2.w * A2[c + 3];
            pt += wt1.x * A1[c] + wt1.y * A1[c + 1] + wt1.z * A1[c + 2] + wt1.w * A1[c + 3];
            pt += wt2.x * A2[c] + wt2.y * A2[c + 1] + wt2.z * A2[c + 2] + wt2.w * A2[c + 3];
        }
        hbase[j] = __ldg(&g_bb1[om]) + pm + __shfl_xor_sync(FULL, pt, 1);
    }

    // ================= phase 2: per-view MLPs; S, U=Sum(vis2 x), V=Sum(vis2 x^2) ==========
    float U[16], Vv[16];
    float S = 0.f;
    #pragma unroll
    for (int c = 0; c < 16; ++c) { U[c] = 0.f; Vv[c] = 0.f; }

    #pragma unroll 1
    for (int n = 0; n < NVIEW; ++n) {
        const int bn = b * NVIEW + n;
        const float mval = __ldg(&mask[bn * G3 + v]);
        const float wn   = mval * minv;

        // --- recompute rde + f (own 16 channels) ---
        const float i0 = __ldg(&vdir[(bn * 3 + 0) * G3 + v]);
        const float i1 = __ldg(&vdir[(bn * 3 + 1) * G3 + v]);
        const float i2 = __ldg(&vdir[(bn * 3 + 2) * G3 + v]);
        const float i3 = __ldg(&depth[bn * G3 + v]);

        float h16o[8];
        #pragma unroll
        for (int j = 0; j < 8; ++j) {
            const int o = hc8 + j;
            const float4 w = *reinterpret_cast<const float4*>(&s_rw1[o * 4]);
            h16o[j] = elu_f(s_rb1[o] + w.x * i0 + w.y * i1 + w.z * i2 + w.w * i3);
        }

        float f[16];
        const float* fbase = &features[(bn * 32 + hc16) * G3 + v];
        #pragma unroll
        for (int j = 0; j < 16; ++j) {
            const int om = hc16 + j, ot = oc16 + j;
            const float pm = sdot<8>(&s_rw2[om * 16 + hc8], h16o);
            const float pt = sdot<8>(&s_rw2[ot * 16 + hc8], h16o);
            f[j] = __ldg(&fbase[j * G3])
                 + elu_f(s_rb2[om] + pm + __shfl_xor_sync(FULL, pt, 1));
        }

        // --- base layer1: my 32 of 64 hidden; partials over my 16 f ---
        float hwn[32];
        #pragma unroll
        for (int j = 0; j < 32; ++j) {
            const int om = hc32 + j, ot = oc32 + j;
            const float pm = sdot<16>(&s_bw1f[om * 32 + hc16], f);
            const float pt = sdot<16>(&s_bw1f[ot * 32 + hc16], f);
            hwn[j] = elu_f(hbase[j] + pm + __shfl_xor_sync(FULL, pt, 1));
        }

        // --- base layer2: my 16 of 32 outputs; partials over my 32 h ---
        float xx[16];
        #pragma unroll
        for (int j = 0; j < 16; ++j) {
            const int om = hc16 + j, ot = oc16 + j;
            const float pm = sdot<32>(&s_bw2[om * 64 + hc32], hwn);
            const float pt = sdot<32>(&s_bw2[ot * 64 + hc32], hwn);
            xx[j] = elu_f(s_bb2[om] + pm + __shfl_xor_sync(FULL, pt, 1));
        }

        // --- vis layer1: t = xx*wn ; hv = elu(vw1.t) ---
        float t[16];
        #pragma unroll
        for (int c = 0; c < 16; ++c) t[c] = xx[c] * wn;

        float hv[16];
        #pragma unroll
        for (int j = 0; j < 16; ++j) {
            const int om = hc16 + j, ot = oc16 + j;
            const float pm = sdot<16>(&s_vw1[om * 32 + hc16], t);
            const float pt = sdot<16>(&s_vw1[ot * 32 + hc16], t);
            hv[j] = elu_f(s_vb1[om] + pm + __shfl_xor_sync(FULL, pt, 1));
        }

        // --- vis layer2 (33 outputs): 32 residual + 1 vis scalar ---
        #pragma unroll
        for (int j = 0; j < 16; ++j) {
            const int om = hc16 + j, ot = oc16 + j;
            const float pm = sdot<16>(&s_vw2[om * 32 + hc16], hv);
            const float pt = sdot<16>(&s_vw2[ot * 32 + hc16], hv);
            xx[j] += elu_f(s_vb2[om] + pm + __shfl_xor_sync(FULL, pt, 1));
        }
        const float pva = sdot<16>(&s_vw2[32 * 32 + hc16], hv);
        const float va  = s_vb2[32] + pva + __shfl_xor_sync(FULL, pva, 1);
        const float vis = sigm_f(elu_f(va)) * mval;

        // --- vis2: t2 = xx*vis ; h2 = elu(v2w1.t2) ; s2 = v2b2 + v2w2.h2 ---
        #pragma unroll
        for (int c = 0; c < 16; ++c) t[c] = xx[c] * vis;

        float h2[16];
        #pragma unroll
        for (int j = 0; j < 16; ++j) {
            const int om = hc16 + j, ot = oc16 + j;
            const float pm = sdot<16>(&s_v2w1[om * 32 + hc16], t);
            const float pt = sdot<16>(&s_v2w1[ot * 32 + hc16], t);
            h2[j] = elu_f(s_v2b1[om] + pm + __shfl_xor_sync(FULL, pt, 1));
        }
        float ps2 = 0.f;
        #pragma unroll
        for (int j = 0; j < 16; ++j) ps2 += s_v2w2[hc16 + j] * h2[j];
        const float s2   = v2b2 + ps2 + __shfl_xor_sync(FULL, ps2, 1);
        const float vis2 = sigm_f(s2) * mval;

        S += vis2;
        #pragma unroll
        for (int c = 0; c < 16; ++c) {
            U[c]  += vis2 * xx[c];
            Vv[c] += vis2 * xx[c] * xx[c];
        }
    }

    // ================= second mean/var + stat head =================
    const float Sinv  = 1.f / (S + EPS);
    const float w2s   = S * Sinv;
    const float wmean = w2s * 0.125f;

    #pragma unroll
    for (int c = 0; c < 16; ++c) {
        const float m2 = U[c] * Sinv;
        U[c]  = m2;                                    // mean2 (own 16)
        Vv[c] = Vv[c] * Sinv - m2 * m2 * (2.f - w2s);  // var2  (own 16)
    }

    #pragma unroll
    for (int j = 0; j < 16; ++j) {
        const int om = hc16 + j, ot = oc16 + j;
        const float pm = sdot<16>(&s_sw[om * 68 + hc16], U) + sdot<16>(&s_sw[om * 68 + 32 + hc16], Vv);
        const float pt = sdot<16>(&s_sw[ot * 68 + hc16], U) + sdot<16>(&s_sw[ot * 68 + 32 + hc16], Vv);
        float acc = s_sb[om] + pm + __shfl_xor_sync(FULL, pt, 1) + s_sw[om * 68 + 64] * wmean;
        out[(b * 32 + om) * G3 + v] = elu_f(acc);
    }
}

extern "C" void kernel_launch(void* const* d_in, const int* in_sizes, int n_in,
                              void* d_out, int out_size) {
    (void)in_sizes; (void)n_in; (void)out_size;
    const float* features = (const float*)d_in[0];
    const float* mask     = (const float*)d_in[1];
    const float* depth    = (const float*)d_in[2];
    const float* vdir     = (const float*)d_in[3];
    const float* rde_w1   = (const float*)d_in[4];
    const float* rde_b1   = (const float*)d_in[5];
    const float* rde_w2   = (const float*)d_in[6];
    const float* rde_b2   = (const float*)d_in[7];
    const float* base_w1  = (const float*)d_in[8];
    const float* base_b1  = (const float*)d_in[9];
    const float* base_w2  = (const float*)d_in[10];
    const float* base_b2  = (const float*)d_in[11];
    const float* vis_w1   = (const float*)d_in[12];
    const float* vis_b1   = (const float*)d_in[13];
    const float* vis_w2   = (const float*)d_in[14];
    const float* vis_b2   = (const float*)d_in[15];
    const float* vis2_w1  = (const float*)d_in[16];
    const float* vis2_b1  = (const float*)d_in[17];
    const float* vis2_w2  = (const float*)d_in[18];
    const float* vis2_b2  = (const float*)d_in[19];
    const float* stat_w   = (const float*)d_in[20];
    const float* stat_b   = (const float*)d_in[21];
    float* out = (float*)d_out;

    // 131072 threads (2 per voxel site): 1024 blocks x 128 threads
    ibr_agg_pair_kernel<<<1024, 128>>>(
        features, mask, depth, vdir,
        rde_w1, rde_b1, rde_w2, rde_b2,
        base_w1, base_b1, base_w2, base_b2,
        vis_w1, vis_b1, vis_w2, vis_b2,
        vis2_w1, vis2_b1, vis2_w2, vis2_b2,
        stat_w, stat_b, out);
}

// round 8
// speedup vs baseline: 1.5370x; 1.4524x over previous
#include <cuda_runtime.h>
#include <math.h>

#define G3 32768
#define NVIEW 8

typedef unsigned long long ull;

__device__ __forceinline__ float elu_f(float x)  { return x > 0.f ? x : (__expf(x) - 1.f); }
__device__ __forceinline__ float sigm_f(float x) { return 1.f / (1.f + __expf(-x)); }

__device__ __forceinline__ ull pk2(float lo, float hi) {
    ull r; asm("mov.b64 %0, {%1, %2};" : "=l"(r) : "f"(lo), "f"(hi)); return r;
}
__device__ __forceinline__ float2 upk2(ull a) {
    float lo, hi; asm("mov.b64 {%0, %1}, %2;" : "=f"(lo), "=f"(hi) : "l"(a));
    return make_float2(lo, hi);
}
__device__ __forceinline__ ull fma2(ull a, ull b, ull c) {
    ull d; asm("fma.rn.f32x2 %0, %1, %2, %3;" : "=l"(d) : "l"(a), "l"(b), "l"(c)); return d;
}
__device__ __forceinline__ ull mul2(ull a, ull b) {
    ull d; asm("mul.rn.f32x2 %0, %1, %2;" : "=l"(d) : "l"(a), "l"(b)); return d;
}
__device__ __forceinline__ ull add2(ull a, ull b) {
    ull d; asm("add.rn.f32x2 %0, %1, %2;" : "=l"(d) : "l"(a), "l"(b)); return d;
}
__device__ __forceinline__ float hsum2(ull a) { float2 f = upk2(a); return f.x + f.y; }

// Packed dot over NP f32x2 pairs (NP even). wr must be 16B-aligned; weights are
// channel-contiguous so a 16B load yields two packed operands directly.
template<int NP>
__device__ __forceinline__ float pdot(const float* __restrict__ wr, const ull* __restrict__ xp) {
    ull a0 = 0ull, a1 = 0ull;
    #pragma unroll
    for (int k = 0; k < NP / 2; ++k) {
        const ulonglong2 w = *reinterpret_cast<const ulonglong2*>(wr + 4 * k);
        a0 = fma2(w.x, xp[2 * k], a0);
        a1 = fma2(w.y, xp[2 * k + 1], a1);
    }
    return hsum2(add2(a0, a1));
}

__global__ __launch_bounds__(128)
void ibr_agg_f32x2_kernel(
    const float* __restrict__ features,   // (B,N,32,G3)
    const float* __restrict__ mask,       // (B,N,1,G3)
    const float* __restrict__ depth,      // (B,N,1,G3)
    const float* __restrict__ vdir,       // (B,N,3,G3)
    const float* __restrict__ g_rw1, const float* __restrict__ g_rb1,   // (16,4),(16)
    const float* __restrict__ g_rw2, const float* __restrict__ g_rb2,   // (32,16),(32)
    const float* __restrict__ g_bw1, const float* __restrict__ g_bb1,   // (64,96),(64)
    const float* __restrict__ g_bw2, const float* __restrict__ g_bb2,   // (32,64),(32)
    const float* __restrict__ g_vw1, const float* __restrict__ g_vb1,   // (32,32),(32)
    const float* __restrict__ g_vw2, const float* __restrict__ g_vb2,   // (33,32),(33)
    const float* __restrict__ g_v2w1, const float* __restrict__ g_v2b1, // (32,32),(32)
    const float* __restrict__ g_v2w2, const float* __restrict__ g_v2b2, // (1,32),(1)
    const float* __restrict__ g_sw,  const float* __restrict__ g_sb,    // (32,65),(32)
    float* __restrict__ out)              // (B,32,G3)
{
    __shared__ __align__(16) float s_rw1[16 * 4];
    __shared__ __align__(16) float s_rb1[16];
    __shared__ __align__(16) float s_rw2[32 * 16];
    __shared__ __align__(16) float s_rb2[32];
    __shared__ __align__(16) float s_bw1f[64 * 32];   // base_w1 cols 64..95 (feat part)
    __shared__ __align__(16) float s_bw2[32 * 64];
    __shared__ __align__(16) float s_bb2[32];
    __shared__ __align__(16) float s_vw1[32 * 32];
    __shared__ __align__(16) float s_vb1[32];
    __shared__ __align__(16) float s_vw2[33 * 32];
    __shared__ __align__(16) float s_vb2[36];
    __shared__ __align__(16) float s_v2w1[32 * 32];
    __shared__ __align__(16) float s_v2b1[32];
    __shared__ __align__(16) float s_v2w2[32];
    __shared__ __align__(16) float s_sw[32 * 68];     // stat_w rows padded 65->68
    __shared__ __align__(16) float s_sb[32];

    const int tid = threadIdx.x;

    for (int i = tid; i < 16 * 4;  i += 128) s_rw1[i] = g_rw1[i];
    if (tid < 16) s_rb1[tid] = g_rb1[tid];
    for (int i = tid; i < 32 * 16; i += 128) s_rw2[i] = g_rw2[i];
    if (tid < 32) s_rb2[tid] = g_rb2[tid];
    for (int i = tid; i < 64 * 32; i += 128) { int o = i >> 5, c = i & 31; s_bw1f[i] = g_bw1[o * 96 + 64 + c]; }
    for (int i = tid; i < 32 * 64; i += 128) s_bw2[i] = g_bw2[i];
    if (tid < 32) s_bb2[tid] = g_bb2[tid];
    for (int i = tid; i < 32 * 32; i += 128) s_vw1[i] = g_vw1[i];
    if (tid < 32) s_vb1[tid] = g_vb1[tid];
    for (int i = tid; i < 33 * 32; i += 128) s_vw2[i] = g_vw2[i];
    if (tid < 33) s_vb2[tid] = g_vb2[tid];
    for (int i = tid; i < 32 * 32; i += 128) s_v2w1[i] = g_v2w1[i];
    if (tid < 32) s_v2b1[tid] = g_v2b1[tid];
    if (tid < 32) s_v2w2[tid] = g_v2w2[tid];
    for (int i = tid; i < 32 * 65; i += 128) { int o = i / 65, c = i % 65; s_sw[o * 68 + c] = g_sw[i]; }
    if (tid < 32) s_sb[tid] = g_sb[tid];
    __syncthreads();

    const float EPS  = 1e-8f;
    const float v2b2 = __ldg(g_v2b2);

    const int gv = blockIdx.x * 128 + tid;   // [0, 65536): (b, voxel)
    const int b  = gv >> 15;
    const int v  = gv & (G3 - 1);

    // ---- mask sum ----
    float msum = 0.f;
    #pragma unroll
    for (int n = 0; n < NVIEW; ++n) msum += __ldg(&mask[(b * NVIEW + n) * G3 + v]);
    const float minv = 1.f / (msum + EPS);
    const float ws   = msum * minv;

    // ================= phase 1: packed A1=Sum(w f), A2=Sum(w f^2) =================
    float fsave[NVIEW][32];            // per-thread local cache of feats
    ull A1p[16], A2p[16];
    #pragma unroll
    for (int j = 0; j < 16; ++j) { A1p[j] = 0ull; A2p[j] = 0ull; }

    #pragma unroll 1
    for (int n = 0; n < NVIEW; ++n) {
        const int bn = b * NVIEW + n;
        const float i0 = __ldg(&vdir[(bn * 3 + 0) * G3 + v]);
        const float i1 = __ldg(&vdir[(bn * 3 + 1) * G3 + v]);
        const float i2 = __ldg(&vdir[(bn * 3 + 2) * G3 + v]);
        const float i3 = __ldg(&depth[bn * G3 + v]);
        const float wn = __ldg(&mask[bn * G3 + v]) * minv;
        const ull  wn2 = pk2(wn, wn);

        ull hp8[8];
        #pragma unroll
        for (int o = 0; o < 16; o += 2) {
            const float4 wa = *reinterpret_cast<const float4*>(&s_rw1[o * 4]);
            const float4 wb = *reinterpret_cast<const float4*>(&s_rw1[(o + 1) * 4]);
            const float ha = elu_f(s_rb1[o]     + wa.x * i0 + wa.y * i1 + wa.z * i2 + wa.w * i3);
            const float hb = elu_f(s_rb1[o + 1] + wb.x * i0 + wb.y * i1 + wb.z * i2 + wb.w * i3);
            hp8[o >> 1] = pk2(ha, hb);
        }

        float fv[32];
        const float* fbase = &features[(bn * 32) * G3 + v];
        #pragma unroll
        for (int c = 0; c < 32; ++c) {
            const float acc = pdot<8>(&s_rw2[c * 16], hp8);
            fv[c] = __ldg(&fbase[c * G3]) + elu_f(s_rb2[c] + acc);
            fsave[n][c] = fv[c];
        }
        #pragma unroll
        for (int j = 0; j < 16; ++j) {
            const ull fp = pk2(fv[2 * j], fv[2 * j + 1]);
            A1p[j] = fma2(wn2, fp, A1p[j]);
            A2p[j] = fma2(wn2, mul2(fp, fp), A2p[j]);
        }
    }

    // mean/var packed: var = A2 - mean^2 (2 - ws)
    {
        const float nw = -(2.f - ws);
        const ull  nw2 = pk2(nw, nw);
        #pragma unroll
        for (int j = 0; j < 16; ++j) {
            const ull m = A1p[j];
            A2p[j] = fma2(mul2(m, m), nw2, A2p[j]);   // A1p = mean, A2p = var
        }
    }

    // ---- hbase[o] = bb1[o] + bw1[o,0:32].mean + bw1[o,32:64].var (packed dots) ----
    float hbase[64];   // local; re-read per view in phase 2
    #pragma unroll 1
    for (int o = 0; o < 64; ++o) {
        const float* rm = &g_bw1[o * 96];
        hbase[o] = __ldg(&g_bb1[o]) + pdot<16>(rm, A1p) + pdot<16>(rm + 32, A2p);
    }

    // ================= phase 2: per-view MLPs; S, Up=Sum(vis2 x), Vvp=Sum(vis2 x^2) =====
    ull Up[16], Vvp[16];
    float S = 0.f;
    #pragma unroll
    for (int j = 0; j < 16; ++j) { Up[j] = 0ull; Vvp[j] = 0ull; }

    #pragma unroll 1
    for (int n = 0; n < NVIEW; ++n) {
        const int bn = b * NVIEW + n;
        const float mval = __ldg(&mask[bn * G3 + v]);
        const float wn   = mval * minv;

        ull fp[16];
        #pragma unroll
        for (int j = 0; j < 16; ++j) fp[j] = pk2(fsave[n][2 * j], fsave[n][2 * j + 1]);

        // --- base: h = elu(hbase + bw1f.f) (64); xx = elu(bb2 + bw2.h) (32); 16-chunks ---
        float xx[32];
        #pragma unroll
        for (int j = 0; j < 32; ++j) xx[j] = s_bb2[j];

        #pragma unroll 1
        for (int oc = 0; oc < 4; ++oc) {
            const int o16 = oc * 16;
            ull hp[8];
            #pragma unroll
            for (int k = 0; k < 16; k += 2) {
                const float ha = elu_f(hbase[o16 + k]     + pdot<16>(&s_bw1f[(o16 + k) * 32], fp));
                const float hb = elu_f(hbase[o16 + k + 1] + pdot<16>(&s_bw1f[(o16 + k + 1) * 32], fp));
                hp[k >> 1] = pk2(ha, hb);
            }
            #pragma unroll
            for (int j = 0; j < 32; ++j)
                xx[j] += pdot<8>(&s_bw2[j * 64 + o16], hp);
        }
        ull xxp[16];
        #pragma unroll
        for (int j = 0; j < 16; ++j)
            xxp[j] = pk2(elu_f(xx[2 * j]), elu_f(xx[2 * j + 1]));

        // --- vis: t = xx*wn ; hv = elu(vw1.t) ; xx += elu(vb2 + vw2.hv) ; va ---
        const ull wn2 = pk2(wn, wn);
        ull tp[16];
        #pragma unroll
        for (int j = 0; j < 16; ++j) tp[j] = mul2(xxp[j], wn2);

        ull hvp[16];
        #pragma unroll
        for (int o = 0; o < 32; o += 2) {
            const float a = elu_f(s_vb1[o]     + pdot<16>(&s_vw1[o * 32], tp));
            const float c = elu_f(s_vb1[o + 1] + pdot<16>(&s_vw1[(o + 1) * 32], tp));
            hvp[o >> 1] = pk2(a, c);
        }

        #pragma unroll
        for (int j = 0; j < 32; j += 2) {
            const float a = elu_f(s_vb2[j]     + pdot<16>(&s_vw2[j * 32], hvp));
            const float c = elu_f(s_vb2[j + 1] + pdot<16>(&s_vw2[(j + 1) * 32], hvp));
            xxp[j >> 1] = add2(xxp[j >> 1], pk2(a, c));       // x = x + x_res
        }
        const float va  = s_vb2[32] + pdot<16>(&s_vw2[32 * 32], hvp);
        const float vis = sigm_f(elu_f(va)) * mval;

        // --- vis2: t2 = xx*vis ; s2 = v2b2 + v2w2.elu(v2w1.t2) ---
        const ull visd = pk2(vis, vis);
        #pragma unroll
        for (int j = 0; j < 16; ++j) tp[j] = mul2(xxp[j], visd);

        float s2 = v2b2;
        #pragma unroll
        for (int o = 0; o < 32; o += 2) {
            const float a = elu_f(s_v2b1[o]     + pdot<16>(&s_v2w1[o * 32], tp));
            const float c = elu_f(s_v2b1[o + 1] + pdot<16>(&s_v2w1[(o + 1) * 32], tp));
            s2 += s_v2w2[o] * a + s_v2w2[o + 1] * c;
        }
        const float vis2 = sigm_f(s2) * mval;

        S += vis2;
        const ull v2d = pk2(vis2, vis2);
        #pragma unroll
        for (int j = 0; j < 16; ++j) {
            Up[j]  = fma2(v2d, xxp[j], Up[j]);
            Vvp[j] = fma2(v2d, mul2(xxp[j], xxp[j]), Vvp[j]);
        }
    }

    // ================= second mean/var + stat head (packed) =================
    const float Sinv  = 1.f / (S + EPS);
    const float w2s   = S * Sinv;
    const float wmean = w2s * 0.125f;
    {
        const ull sd  = pk2(Sinv, Sinv);
        const float nw = -(2.f - w2s);
        const ull nw2 = pk2(nw, nw);
        #pragma unroll
        for (int j = 0; j < 16; ++j) {
            const ull m2 = mul2(Up[j], sd);
            Up[j]  = m2;                                        // mean2
            Vvp[j] = fma2(mul2(m2, m2), nw2, mul2(Vvp[j], sd)); // var2
        }
    }

    #pragma unroll 1
    for (int o = 0; o < 32; ++o) {
        const float* wr = &s_sw[o * 68];
        float acc = s_sb[o] + pdot<16>(wr, Up) + pdot<16>(wr + 32, Vvp) + wr[64] * wmean;
        out[(b * 32 + o) * G3 + v] = elu_f(acc);
    }
}

extern "C" void kernel_launch(void* const* d_in, const int* in_sizes, int n_in,
                              void* d_out, int out_size) {
    (void)in_sizes; (void)n_in; (void)out_size;
    const float* features = (const float*)d_in[0];
    const float* mask     = (const float*)d_in[1];
    const float* depth    = (const float*)d_in[2];
    const float* vdir     = (const float*)d_in[3];
    const float* rde_w1   = (const float*)d_in[4];
    const float* rde_b1   = (const float*)d_in[5];
    const float* rde_w2   = (const float*)d_in[6];
    const float* rde_b2   = (const float*)d_in[7];
    const float* base_w1  = (const float*)d_in[8];
    const float* base_b1  = (const float*)d_in[9];
    const float* base_w2  = (const float*)d_in[10];
    const float* base_b2  = (const float*)d_in[11];
    const float* vis_w1   = (const float*)d_in[12];
    const float* vis_b1   = (const float*)d_in[13];
    const float* vis_w2   = (const float*)d_in[14];
    const float* vis_b2   = (const float*)d_in[15];
    const float* vis2_w1  = (const float*)d_in[16];
    const float* vis2_b1  = (const float*)d_in[17];
    const float* vis2_w2  = (const float*)d_in[18];
    const float* vis2_b2  = (const float*)d_in[19];
    const float* stat_w   = (const float*)d_in[20];
    const float* stat_b   = (const float*)d_in[21];
    float* out = (float*)d_out;

    ibr_agg_f32x2_kernel<<<512, 128>>>(
        features, mask, depth, vdir,
        rde_w1, rde_b1, rde_w2, rde_b2,
        base_w1, base_b1, base_w2, base_b2,
        vis_w1, vis_b1, vis_w2, vis_b2,
        vis2_w1, vis2_b1, vis2_w2, vis2_b2,
        stat_w, stat_b, out);
}